// round 6
// baseline (speedup 1.0000x reference)
#include <cuda_runtime.h>
#include <math.h>
#include <cstdint>

#define NA 20000
#define NP 50000
#define EMAX 300000
#define DD 256
#define NH 8
#define DKH 32

// ---------------- scratch (static __device__ globals) ----------------
__device__ float g_Har[NA * DD];
__device__ float g_Hpr[NP * DD];
__device__ float g_K0[NA * DD];
__device__ float g_V0[NA * DD];
__device__ float g_Qa[NA * DD];
__device__ float g_Kp[NP * DD];
__device__ float g_Vp[NP * DD];
__device__ float g_Qp[NP * DD];
__device__ float g_Qpc[NP * DD];
__device__ float g_aggPw[NP * DD];
__device__ float g_aggPc[NP * DD];
__device__ float g_aggP[NP * DD];
__device__ float g_aggAc[NA * DD];
__device__ float g_aggA[NA * DD];
__device__ float g_fW[3 * DD * DD];
__device__ float g_fB[3 * DD];
__device__ float g_rw[5 * DD * DD];
__device__ int g_deg0[NP];
__device__ int g_deg1[NP];
__device__ int g_deg2[NA];
__device__ int g_rp0[NP + 1];
__device__ int g_rp1[NP + 1];
__device__ int g_rp2[NA + 1];
__device__ int g_cur0[NP];
__device__ int g_cur1[NP];
__device__ int g_cur2[NA];
__device__ int g_col0[EMAX];
__device__ int g_col1[EMAX];
__device__ int g_col2[EMAX];

__device__ __forceinline__ float tf32r(float v) {
    uint32_t r;
    asm("cvt.rna.tf32.f32 %0, %1;" : "=r"(r) : "f"(v));
    return __uint_as_float(r);
}

// ---------------- round-copy (tf32 pre-rounding) ----------------
__global__ void roundcopy(const float* __restrict__ in, float* __restrict__ out, int n4) {
    int i = blockIdx.x * blockDim.x + threadIdx.x;
    if (i < n4) {
        float4 v = ((const float4*)in)[i];
        v.x = tf32r(v.x); v.y = tf32r(v.y); v.z = tf32r(v.z); v.w = tf32r(v.w);
        ((float4*)out)[i] = v;
    }
}

// ---------------- weight folds ----------------
__global__ void fold_k(const float* __restrict__ W, const float* __restrict__ rel,
                       const float* __restrict__ b,
                       float* __restrict__ Wout, float* __restrict__ bout) {
    int c = blockIdx.x, d = threadIdx.x;
    int h = c >> 5, j = c & 31;
    float s = 0.f;
#pragma unroll
    for (int i = 0; i < 32; i++)
        s += rel[(h * 32 + i) * 32 + j] * W[(h * 32 + i) * DD + d];
    Wout[c * DD + d] = tf32r(s);
    if (d == 0) {
        float sb = 0.f;
#pragma unroll
        for (int i = 0; i < 32; i++)
            sb += rel[(h * 32 + i) * 32 + j] * b[h * 32 + i];
        bout[c] = sb;
    }
}

__global__ void fold_q(const float* __restrict__ W, const float* __restrict__ rel,
                       const float* __restrict__ b,
                       float* __restrict__ Wout, float* __restrict__ bout) {
    int c = blockIdx.x, d = threadIdx.x;
    int h = c >> 5, i = c & 31;
    float s = 0.f;
#pragma unroll
    for (int j = 0; j < 32; j++)
        s += rel[(h * 32 + i) * 32 + j] * W[(h * 32 + j) * DD + d];
    Wout[c * DD + d] = tf32r(s);
    if (d == 0) {
        float sb = 0.f;
#pragma unroll
        for (int j = 0; j < 32; j++)
            sb += rel[(h * 32 + i) * 32 + j] * b[h * 32 + j];
        bout[c] = sb;
    }
}

// ---------------- block-diagonal per-head transform ----------------
__global__ void bdtrans(const float* __restrict__ in, const float* __restrict__ base,
                        const float* __restrict__ R, float* __restrict__ out,
                        int N, int transp, int roundit) {
    __shared__ float Rs[32 * 33];
    __shared__ float As[64 * 33];
    const int h = blockIdx.y;
    const int n0 = blockIdx.x * 64;
    const int t = threadIdx.x;
#pragma unroll
    for (int k = 0; k < 4; k++) {
        int idx = t * 4 + k;
        int i0 = idx >> 5, j0 = idx & 31;
        float v = R[h * 1024 + idx];
        if (transp) Rs[i0 * 33 + j0] = v;
        else        Rs[j0 * 33 + i0] = v;
    }
    const int rows = (N - n0 < 64) ? (N - n0) : 64;
#pragma unroll
    for (int it = 0; it < 8; it++) {
        int r = (t >> 5) + it * 8;
        int j = t & 31;
        if (r < rows) As[r * 33 + j] = in[(size_t)(n0 + r) * DD + h * 32 + j];
    }
    __syncthreads();
    const int i = t & 31;
#pragma unroll
    for (int it = 0; it < 8; it++) {
        int r = (t >> 5) + it * 8;
        if (r >= rows) break;
        float v = 0.f;
#pragma unroll
        for (int j = 0; j < 32; j++) v += As[r * 33 + j] * Rs[j * 33 + i];
        size_t o = (size_t)(n0 + r) * DD + h * 32 + i;
        if (base) v += base[o];
        out[o] = roundit ? tf32r(v) : v;
    }
}

// ---------------- tf32 mma GEMM with ldmatrix fragments ----------------
#define SLAB_F (128 * 36)
#define GSMEM (4 * SLAB_F * 4)

__device__ __forceinline__ void mma1688(float c[4], const uint32_t a[4], const uint32_t b[2]) {
    asm volatile(
        "mma.sync.aligned.m16n8k8.row.col.f32.tf32.tf32.f32 "
        "{%0,%1,%2,%3}, {%4,%5,%6,%7}, {%8,%9}, {%0,%1,%2,%3};"
        : "+f"(c[0]), "+f"(c[1]), "+f"(c[2]), "+f"(c[3])
        : "r"(a[0]), "r"(a[1]), "r"(a[2]), "r"(a[3]), "r"(b[0]), "r"(b[1]));
}

__global__ __launch_bounds__(256) void gemm_mma(
    const float* __restrict__ A, const float* __restrict__ B,
    const float* __restrict__ bias, const float* __restrict__ resid,
    const float* __restrict__ skipv, int nid,
    float* __restrict__ C, int M) {
    extern __shared__ float sm[];
    const int tid = threadIdx.x;
    const int m0 = blockIdx.x * 128;
    const int col0 = blockIdx.y * 128;
    const int w = tid >> 5, ln = tid & 31;
    const int rowb = (w >> 2) * 64, colb = (w & 3) * 32;
    const int lg = ln >> 2, lt = ln & 3;

    float* const Ab[2] = {sm, sm + SLAB_F};
    float* const Bb[2] = {sm + 2 * SLAB_F, sm + 3 * SLAB_F};

    float c[4][4][4];
#pragma unroll
    for (int mi = 0; mi < 4; mi++)
#pragma unroll
        for (int ni = 0; ni < 4; ni++)
#pragma unroll
            for (int r = 0; r < 4; r++) c[mi][ni][r] = 0.f;

    auto load_slab = [&](int s, int b) {
        const int k0 = s * 32;
        float* As = Ab[b];
        float* Bs = Bb[b];
#pragma unroll
        for (int i = 0; i < 4; i++) {
            int idx = tid + i * 256;
            int row = idx >> 3, kg = idx & 7;
            uint32_t da = (uint32_t)__cvta_generic_to_shared(As + row * 36 + kg * 4);
            const float* ga = A + (size_t)(m0 + row) * DD + k0 + kg * 4;
            int sz = ((m0 + row) < M) ? 16 : 0;
            asm volatile("cp.async.cg.shared.global [%0], [%1], 16, %2;\n" ::"r"(da), "l"(ga), "r"(sz));
            uint32_t db = (uint32_t)__cvta_generic_to_shared(Bs + row * 36 + kg * 4);
            const float* gb = B + (size_t)(col0 + row) * DD + k0 + kg * 4;
            asm volatile("cp.async.cg.shared.global [%0], [%1], 16;\n" ::"r"(db), "l"(gb));
        }
        asm volatile("cp.async.commit_group;\n");
    };

    // per-lane ldmatrix row offsets (floats)
    const int aRowOff = (rowb + (ln & 15)) * 36 + ((ln & 16) ? 4 : 0);
    const int bRowOff = (colb + (ln & 7) + ((ln & 16) ? 8 : 0)) * 36 + ((ln & 8) ? 4 : 0);

    load_slab(0, 0);
    for (int s = 0; s < 8; s++) {
        int b = s & 1;
        if (s < 7) {
            load_slab(s + 1, b ^ 1);
            asm volatile("cp.async.wait_group 1;\n");
        } else {
            asm volatile("cp.async.wait_group 0;\n");
        }
        __syncthreads();
        const uint32_t aB = (uint32_t)__cvta_generic_to_shared(Ab[b] + aRowOff);
        const uint32_t bB = (uint32_t)__cvta_generic_to_shared(Bb[b] + bRowOff);
#pragma unroll
        for (int ks = 0; ks < 4; ks++) {
            uint32_t af[4][4], bf[4][2];
#pragma unroll
            for (int mi = 0; mi < 4; mi++) {
                uint32_t ad = aB + (uint32_t)((mi * 16 * 36 + ks * 8) * 4);
                asm volatile("ldmatrix.sync.aligned.m8n8.x4.shared.b16 {%0,%1,%2,%3}, [%4];"
                             : "=r"(af[mi][0]), "=r"(af[mi][1]), "=r"(af[mi][2]), "=r"(af[mi][3])
                             : "r"(ad));
            }
#pragma unroll
            for (int np = 0; np < 2; np++) {
                uint32_t bd = bB + (uint32_t)((np * 16 * 36 + ks * 8) * 4);
                asm volatile("ldmatrix.sync.aligned.m8n8.x4.shared.b16 {%0,%1,%2,%3}, [%4];"
                             : "=r"(bf[2 * np][0]), "=r"(bf[2 * np][1]),
                               "=r"(bf[2 * np + 1][0]), "=r"(bf[2 * np + 1][1])
                             : "r"(bd));
            }
#pragma unroll
            for (int mi = 0; mi < 4; mi++)
#pragma unroll
                for (int ni = 0; ni < 4; ni++) mma1688(c[mi][ni], af[mi], bf[ni]);
        }
        __syncthreads();
    }

    float alpha = 1.f, beta = 0.f;
    if (resid) {
        float sv = skipv[nid];
        alpha = 1.f / (1.f + __expf(-sv));
        beta = 1.f - alpha;
    }
#pragma unroll
    for (int mi = 0; mi < 4; mi++) {
#pragma unroll
        for (int half = 0; half < 2; half++) {
            int row = m0 + rowb + mi * 16 + lg + half * 8;
            if (row >= M) continue;
#pragma unroll
            for (int ni = 0; ni < 4; ni++) {
                int cc = col0 + colb + ni * 8 + lt * 2;
                float2 o;
                o.x = c[mi][ni][half * 2 + 0] + bias[cc];
                o.y = c[mi][ni][half * 2 + 1] + bias[cc + 1];
                if (resid) {
                    float2 rv = *(const float2*)(resid + (size_t)row * DD + cc);
                    o.x = o.x * alpha + rv.x * beta;
                    o.y = o.y * alpha + rv.y * beta;
                }
                *(float2*)(C + (size_t)row * DD + cc) = o;
            }
        }
    }
}

// ---------------- CSR build (merged) ----------------
__global__ void zero3(int* d0, int* d1, int* d2) {
    int i = blockIdx.x * blockDim.x + threadIdx.x;
    if (i < NP) { d0[i] = 0; d1[i] = 0; }
    if (i < NA) d2[i] = 0;
}

__global__ void hist3(const int* __restrict__ dw, const int* __restrict__ dc,
                      const int* __restrict__ db, int E,
                      int* d0, int* d1, int* d2) {
    int i = blockIdx.x * blockDim.x + threadIdx.x;
    if (i < E) atomicAdd(&d0[dw[i]], 1);
    else if (i < 2 * E) atomicAdd(&d1[dc[i - E]], 1);
    else if (i < 3 * E) atomicAdd(&d2[db[i - 2 * E]], 1);
}

__global__ void scan3(const int* __restrict__ deg0, const int* __restrict__ deg1,
                      const int* __restrict__ deg2,
                      int* rp0, int* rp1, int* rp2, int* c0, int* c1, int* c2) {
    __shared__ int sh[1024];
    __shared__ int carry_s;
    const int* deg; int* rp; int* cur; int n;
    if (blockIdx.x == 0) { deg = deg0; rp = rp0; cur = c0; n = NP; }
    else if (blockIdx.x == 1) { deg = deg1; rp = rp1; cur = c1; n = NP; }
    else { deg = deg2; rp = rp2; cur = c2; n = NA; }
    int tid = threadIdx.x;
    if (tid == 0) carry_s = 0;
    __syncthreads();
    for (int base = 0; base < n; base += 1024) {
        int i = base + tid;
        int v = (i < n) ? deg[i] : 0;
        sh[tid] = v;
        __syncthreads();
        for (int off = 1; off < 1024; off <<= 1) {
            int t = (tid >= off) ? sh[tid - off] : 0;
            __syncthreads();
            sh[tid] += t;
            __syncthreads();
        }
        int incl = sh[tid] + carry_s;
        if (i < n) { rp[i + 1] = incl; cur[i] = incl - v; }
        __syncthreads();
        if (tid == 1023) carry_s = incl;
        __syncthreads();
    }
    if (tid == 0) rp[0] = 0;
}

__global__ void scatter3(const int* __restrict__ sw, const int* __restrict__ dw,
                         const int* __restrict__ sc, const int* __restrict__ dc,
                         const int* __restrict__ sb, const int* __restrict__ db, int E,
                         int* c0, int* c1, int* c2,
                         int* col0, int* col1, int* col2) {
    int i = blockIdx.x * blockDim.x + threadIdx.x;
    if (i < E) { int p = atomicAdd(&c0[dw[i]], 1); col0[p] = sw[i]; }
    else if (i < 2 * E) { int j = i - E; int p = atomicAdd(&c1[dc[j]], 1); col1[p] = sc[j]; }
    else if (i < 3 * E) { int j = i - 2 * E; int p = atomicAdd(&c2[db[j]], 1); col2[p] = sb[j]; }
}

// ---------------- per-dst online-softmax aggregation (1 expf per edge-head) ----------------
__device__ __forceinline__ void csr_attend(
    int d, int lane, const int* __restrict__ rp, const int* __restrict__ colv,
    const float* __restrict__ K, const float* __restrict__ V,
    const float pri[NH], const float q[NH], float acc[NH]) {
    float m[NH], s[NH], a[NH];
#pragma unroll
    for (int h = 0; h < NH; h++) { m[h] = -1e30f; s[h] = 0.f; a[h] = 0.f; }
    int beg = rp[d], end = rp[d + 1];
    for (int e = beg; e < end; e++) {
        int src = colv[e];
        const float* kr = K + (size_t)src * DD;
        const float* vr = V + (size_t)src * DD;
        float p[NH];
#pragma unroll
        for (int h = 0; h < NH; h++) p[h] = q[h] * kr[h * DKH + lane];
#pragma unroll
        for (int off = 16; off; off >>= 1)
#pragma unroll
            for (int h = 0; h < NH; h++) p[h] += __shfl_xor_sync(0xffffffffu, p[h], off);
#pragma unroll
        for (int h = 0; h < NH; h++) {
            float sc = p[h] * pri[h];
            float v = vr[h * DKH + lane];
            if (sc <= m[h]) {  // warp-uniform branch (sc identical across lanes)
                float wgt = __expf(sc - m[h]);
                s[h] += wgt;
                a[h] += wgt * v;
            } else {
                float f = __expf(m[h] - sc);  // first edge: exp(-inf)=0
                s[h] = s[h] * f + 1.f;
                a[h] = a[h] * f + v;
                m[h] = sc;
            }
        }
    }
#pragma unroll
    for (int h = 0; h < NH; h++)
        if (s[h] > 0.f) acc[h] += a[h] / s[h];
}

__global__ void agg_paper_kernel(const float* __restrict__ Qp, const float* __restrict__ Qpc,
                                 const float* __restrict__ K0, const float* __restrict__ V0,
                                 const float* __restrict__ Kp, const float* __restrict__ Vp,
                                 const int* __restrict__ rp0, const int* __restrict__ col0,
                                 const int* __restrict__ rp1, const int* __restrict__ col1,
                                 const float* __restrict__ rel_pri,
                                 float* __restrict__ aggw, float* __restrict__ aggc) {
    int w = (blockIdx.x * blockDim.x + threadIdx.x) >> 5;
    int lane = threadIdx.x & 31;
    if (w >= NP) return;
    const float sc = 0.17677669529663687f;
    float q0[NH], qc[NH], accw[NH], accc[NH], pri0[NH], pri1[NH];
#pragma unroll
    for (int h = 0; h < NH; h++) {
        q0[h] = Qp[(size_t)w * DD + h * DKH + lane];
        qc[h] = Qpc[(size_t)w * DD + h * DKH + lane];
        accw[h] = 0.f; accc[h] = 0.f;
        pri0[h] = rel_pri[h] * sc;
        pri1[h] = rel_pri[NH + h] * sc;
    }
    csr_attend(w, lane, rp0, col0, K0, V0, pri0, q0, accw);
    csr_attend(w, lane, rp1, col1, Kp, Vp, pri1, qc, accc);
#pragma unroll
    for (int h = 0; h < NH; h++) {
        aggw[(size_t)w * DD + h * DKH + lane] = accw[h];
        aggc[(size_t)w * DD + h * DKH + lane] = accc[h];
    }
}

__global__ void agg_author_kernel(const float* __restrict__ Qa,
                                  const float* __restrict__ Kp, const float* __restrict__ Vp,
                                  const int* __restrict__ rp2, const int* __restrict__ col2,
                                  const float* __restrict__ rel_pri,
                                  float* __restrict__ agg) {
    int w = (blockIdx.x * blockDim.x + threadIdx.x) >> 5;
    int lane = threadIdx.x & 31;
    if (w >= NA) return;
    const float sc = 0.17677669529663687f;
    float q[NH], acc[NH], pri2[NH];
#pragma unroll
    for (int h = 0; h < NH; h++) {
        q[h] = Qa[(size_t)w * DD + h * DKH + lane];
        acc[h] = 0.f;
        pri2[h] = rel_pri[2 * NH + h] * sc;
    }
    csr_attend(w, lane, rp2, col2, Kp, Vp, pri2, q, acc);
#pragma unroll
    for (int h = 0; h < NH; h++) agg[(size_t)w * DD + h * DKH + lane] = acc[h];
}

// ---------------- host launch ----------------
extern "C" void kernel_launch(void* const* d_in, const int* in_sizes, int n_in,
                              void* d_out, int out_size) {
    const float* h_author = (const float*)d_in[0];
    const float* h_paper  = (const float*)d_in[1];
    const float* k_w  = (const float*)d_in[2];
    const float* k_b  = (const float*)d_in[3];
    const float* q_w  = (const float*)d_in[4];
    const float* q_b  = (const float*)d_in[5];
    const float* v_w  = (const float*)d_in[6];
    const float* v_b  = (const float*)d_in[7];
    const float* a_w  = (const float*)d_in[8];
    const float* a_b  = (const float*)d_in[9];
    const float* rel_att = (const float*)d_in[10];
    const float* rel_msg = (const float*)d_in[11];
    const float* rel_pri = (const float*)d_in[12];
    const float* skipv   = (const float*)d_in[13];
    const int* src_writes = (const int*)d_in[14];
    const int* dst_writes = (const int*)d_in[15];
    const int* src_cites  = (const int*)d_in[16];
    const int* dst_cites  = (const int*)d_in[17];
    const int* src_wb     = (const int*)d_in[18];
    const int* dst_wb     = (const int*)d_in[19];

    int E = in_sizes[14];
    if (E > EMAX) E = EMAX;

    float *Har, *Hpr, *K0, *V0, *Qa, *Kp, *Vp, *Qp, *Qpc;
    float *aggPw, *aggPc, *aggP, *aggAc, *aggA, *fW, *fB, *rw;
    int *deg0, *deg1, *deg2, *rp0, *rp1, *rp2, *cur0, *cur1, *cur2, *col0, *col1, *col2;
    cudaGetSymbolAddress((void**)&Har, g_Har);
    cudaGetSymbolAddress((void**)&Hpr, g_Hpr);
    cudaGetSymbolAddress((void**)&K0, g_K0);
    cudaGetSymbolAddress((void**)&V0, g_V0);
    cudaGetSymbolAddress((void**)&Qa, g_Qa);
    cudaGetSymbolAddress((void**)&Kp, g_Kp);
    cudaGetSymbolAddress((void**)&Vp, g_Vp);
    cudaGetSymbolAddress((void**)&Qp, g_Qp);
    cudaGetSymbolAddress((void**)&Qpc, g_Qpc);
    cudaGetSymbolAddress((void**)&aggPw, g_aggPw);
    cudaGetSymbolAddress((void**)&aggPc, g_aggPc);
    cudaGetSymbolAddress((void**)&aggP, g_aggP);
    cudaGetSymbolAddress((void**)&aggAc, g_aggAc);
    cudaGetSymbolAddress((void**)&aggA, g_aggA);
    cudaGetSymbolAddress((void**)&fW, g_fW);
    cudaGetSymbolAddress((void**)&fB, g_fB);
    cudaGetSymbolAddress((void**)&rw, g_rw);
    cudaGetSymbolAddress((void**)&deg0, g_deg0);
    cudaGetSymbolAddress((void**)&deg1, g_deg1);
    cudaGetSymbolAddress((void**)&deg2, g_deg2);
    cudaGetSymbolAddress((void**)&rp0, g_rp0);
    cudaGetSymbolAddress((void**)&rp1, g_rp1);
    cudaGetSymbolAddress((void**)&rp2, g_rp2);
    cudaGetSymbolAddress((void**)&cur0, g_cur0);
    cudaGetSymbolAddress((void**)&cur1, g_cur1);
    cudaGetSymbolAddress((void**)&cur2, g_cur2);
    cudaGetSymbolAddress((void**)&col0, g_col0);
    cudaGetSymbolAddress((void**)&col1, g_col1);
    cudaGetSymbolAddress((void**)&col2, g_col2);

    cudaFuncSetAttribute(gemm_mma, cudaFuncAttributeMaxDynamicSharedMemorySize, GSMEM);

    float* kwr1 = rw + 0 * 65536;
    float* vwr1 = rw + 1 * 65536;
    float* qwr1 = rw + 2 * 65536;
    float* awr  = rw + 3 * 65536;
    float* fWk0 = fW + 0 * 65536;
    float* fWv0 = fW + 1 * 65536;
    float* fWqa = fW + 2 * 65536;
    float* fBk0 = fB + 0 * 256;
    float* fBv0 = fB + 1 * 256;
    float* fBqa = fB + 2 * 256;

    // 1) pre-round GEMM inputs to tf32
    roundcopy<<<(NA * DD / 4 + 255) / 256, 256>>>(h_author, Har, NA * DD / 4);
    roundcopy<<<(NP * DD / 4 + 255) / 256, 256>>>(h_paper, Hpr, NP * DD / 4);
    roundcopy<<<(65536 / 4 + 255) / 256, 256>>>(k_w + 65536, kwr1, 65536 / 4);
    roundcopy<<<(65536 / 4 + 255) / 256, 256>>>(v_w + 65536, vwr1, 65536 / 4);
    roundcopy<<<(65536 / 4 + 255) / 256, 256>>>(q_w + 65536, qwr1, 65536 / 4);
    roundcopy<<<(131072 / 4 + 255) / 256, 256>>>(a_w, awr, 131072 / 4);

    // 2) weight folds
    fold_k<<<256, 256>>>(k_w, rel_att, k_b, fWk0, fBk0);
    fold_k<<<256, 256>>>(v_w, rel_msg, v_b, fWv0, fBv0);
    fold_q<<<256, 256>>>(q_w, rel_att + 2 * 8192, q_b, fWqa, fBqa);

    // 3) projection GEMMs
    {
        dim3 ga((NA + 127) / 128, 2), gp((NP + 127) / 128, 2);
        gemm_mma<<<ga, 256, GSMEM>>>(Har, fWk0, fBk0, nullptr, skipv, 0, K0, NA);
        gemm_mma<<<ga, 256, GSMEM>>>(Har, fWv0, fBv0, nullptr, skipv, 0, V0, NA);
        gemm_mma<<<ga, 256, GSMEM>>>(Har, fWqa, fBqa, nullptr, skipv, 0, Qa, NA);
        gemm_mma<<<gp, 256, GSMEM>>>(Hpr, kwr1, k_b + 256, nullptr, skipv, 0, Kp, NP);
        gemm_mma<<<gp, 256, GSMEM>>>(Hpr, vwr1, v_b + 256, nullptr, skipv, 0, Vp, NP);
        gemm_mma<<<gp, 256, GSMEM>>>(Hpr, qwr1, q_b + 256, nullptr, skipv, 1, Qp, NP);
    }

    // 4) Q transform for cites
    {
        dim3 g((NP + 63) / 64, NH);
        bdtrans<<<g, 256>>>(Qp, nullptr, rel_att + 8192, Qpc, NP, 0, 0);
    }

    // 5) CSR builds
    zero3<<<(NP + 255) / 256, 256>>>(deg0, deg1, deg2);
    hist3<<<(3 * E + 255) / 256, 256>>>(dst_writes, dst_cites, dst_wb, E, deg0, deg1, deg2);
    scan3<<<3, 1024>>>(deg0, deg1, deg2, rp0, rp1, rp2, cur0, cur1, cur2);
    scatter3<<<(3 * E + 255) / 256, 256>>>(src_writes, dst_writes, src_cites, dst_cites,
                                           src_wb, dst_wb, E, cur0, cur1, cur2, col0, col1, col2);

    // 6) attention aggregation
    agg_paper_kernel<<<(NP * 32 + 255) / 256, 256>>>(Qp, Qpc, K0, V0, Kp, Vp,
                                                     rp0, col0, rp1, col1, rel_pri, aggPw, aggPc);
    agg_author_kernel<<<(NA * 32 + 255) / 256, 256>>>(Qa, Kp, Vp, rp2, col2, rel_pri, aggAc);

    // 7) post-agg message transforms
    {
        dim3 gp((NP + 63) / 64, NH), ga((NA + 63) / 64, NH);
        bdtrans<<<gp, 256>>>(aggPc, aggPw, rel_msg + 8192, aggP, NP, 1, 1);
        bdtrans<<<ga, 256>>>(aggAc, nullptr, rel_msg + 2 * 8192, aggA, NA, 1, 1);
    }

    // 8) output GEMMs
    float* out = (float*)d_out;
    {
        dim3 ga((NA + 127) / 128, 2), gp((NP + 127) / 128, 2);
        gemm_mma<<<ga, 256, GSMEM>>>(aggA, awr, a_b, h_author, skipv, 0, out, NA);
        gemm_mma<<<gp, 256, GSMEM>>>(aggP, awr + 65536, a_b + 256, h_paper, skipv, 1,
                                     out + (size_t)NA * DD, NP);
    }
}

// round 7
// speedup vs baseline: 1.2959x; 1.2959x over previous
#include <cuda_runtime.h>
#include <math.h>
#include <cstdint>

#define NA 20000
#define NP 50000
#define EMAX 300000
#define DD 256
#define NH 8
#define DKH 32

// ---------------- scratch (static __device__ globals) ----------------
__device__ float g_Har[NA * DD];
__device__ float g_Hpr[NP * DD];
__device__ float g_K0[NA * DD];
__device__ float g_V0[NA * DD];
__device__ float g_Qa[NA * DD];
__device__ float g_Kp[NP * DD];
__device__ float g_Vp[NP * DD];
__device__ float g_Qp[NP * DD];
__device__ float g_Qpc[NP * DD];
__device__ float g_aggPw[NP * DD];
__device__ float g_aggPc[NP * DD];
__device__ float g_aggP[NP * DD];
__device__ float g_aggAc[NA * DD];
__device__ float g_aggA[NA * DD];
__device__ float g_fW[3 * DD * DD];
__device__ float g_fB[3 * DD];
__device__ float g_rw[5 * DD * DD];
__device__ int g_deg0[NP];
__device__ int g_deg1[NP];
__device__ int g_deg2[NA];
__device__ int g_rp0[NP + 1];
__device__ int g_rp1[NP + 1];
__device__ int g_rp2[NA + 1];
__device__ int g_cur0[NP];
__device__ int g_cur1[NP];
__device__ int g_cur2[NA];
__device__ int g_col0[EMAX];
__device__ int g_col1[EMAX];
__device__ int g_col2[EMAX];

__device__ __forceinline__ float tf32r(float v) {
    uint32_t r;
    asm("cvt.rna.tf32.f32 %0, %1;" : "=r"(r) : "f"(v));
    return __uint_as_float(r);
}

// ---------------- round-copy ----------------
__global__ void roundcopy(const float* __restrict__ in, float* __restrict__ out, int n4) {
    int i = blockIdx.x * blockDim.x + threadIdx.x;
    if (i < n4) {
        float4 v = ((const float4*)in)[i];
        v.x = tf32r(v.x); v.y = tf32r(v.y); v.z = tf32r(v.z); v.w = tf32r(v.w);
        ((float4*)out)[i] = v;
    }
}

// ---------------- weight folds ----------------
__global__ void fold_k(const float* __restrict__ W, const float* __restrict__ rel,
                       const float* __restrict__ b,
                       float* __restrict__ Wout, float* __restrict__ bout) {
    int c = blockIdx.x, d = threadIdx.x;
    int h = c >> 5, j = c & 31;
    float s = 0.f;
#pragma unroll
    for (int i = 0; i < 32; i++)
        s += rel[(h * 32 + i) * 32 + j] * W[(h * 32 + i) * DD + d];
    Wout[c * DD + d] = tf32r(s);
    if (d == 0) {
        float sb = 0.f;
#pragma unroll
        for (int i = 0; i < 32; i++)
            sb += rel[(h * 32 + i) * 32 + j] * b[h * 32 + i];
        bout[c] = sb;
    }
}

__global__ void fold_q(const float* __restrict__ W, const float* __restrict__ rel,
                       const float* __restrict__ b,
                       float* __restrict__ Wout, float* __restrict__ bout) {
    int c = blockIdx.x, d = threadIdx.x;
    int h = c >> 5, i = c & 31;
    float s = 0.f;
#pragma unroll
    for (int j = 0; j < 32; j++)
        s += rel[(h * 32 + i) * 32 + j] * W[(h * 32 + j) * DD + d];
    Wout[c * DD + d] = tf32r(s);
    if (d == 0) {
        float sb = 0.f;
#pragma unroll
        for (int j = 0; j < 32; j++)
            sb += rel[(h * 32 + i) * 32 + j] * b[h * 32 + j];
        bout[c] = sb;
    }
}

// ---------------- block-diagonal per-head transform ----------------
__global__ void bdtrans(const float* __restrict__ in, const float* __restrict__ base,
                        const float* __restrict__ R, float* __restrict__ out,
                        int N, int transp, int roundit) {
    __shared__ float Rs[32 * 33];
    __shared__ float As[64 * 33];
    const int h = blockIdx.y;
    const int n0 = blockIdx.x * 64;
    const int t = threadIdx.x;
#pragma unroll
    for (int k = 0; k < 4; k++) {
        int idx = t * 4 + k;
        int i0 = idx >> 5, j0 = idx & 31;
        float v = R[h * 1024 + idx];
        if (transp) Rs[i0 * 33 + j0] = v;
        else        Rs[j0 * 33 + i0] = v;
    }
    const int rows = (N - n0 < 64) ? (N - n0) : 64;
#pragma unroll
    for (int it = 0; it < 8; it++) {
        int r = (t >> 5) + it * 8;
        int j = t & 31;
        if (r < rows) As[r * 33 + j] = in[(size_t)(n0 + r) * DD + h * 32 + j];
    }
    __syncthreads();
    const int i = t & 31;
#pragma unroll
    for (int it = 0; it < 8; it++) {
        int r = (t >> 5) + it * 8;
        if (r >= rows) break;
        float v = 0.f;
#pragma unroll
        for (int j = 0; j < 32; j++) v += As[r * 33 + j] * Rs[j * 33 + i];
        size_t o = (size_t)(n0 + r) * DD + h * 32 + i;
        if (base) v += base[o];
        out[o] = roundit ? tf32r(v) : v;
    }
}

// ---------------- tf32 mma GEMM (single-B, R5-proven) ----------------
#define SLAB_F (128 * 36)
#define GSMEM (4 * SLAB_F * 4)
#define GS3 (8 * SLAB_F * 4)

__device__ __forceinline__ void mma1688(float c[4], const uint32_t a[4], const uint32_t b[2]) {
    asm volatile(
        "mma.sync.aligned.m16n8k8.row.col.f32.tf32.tf32.f32 "
        "{%0,%1,%2,%3}, {%4,%5,%6,%7}, {%8,%9}, {%0,%1,%2,%3};"
        : "+f"(c[0]), "+f"(c[1]), "+f"(c[2]), "+f"(c[3])
        : "r"(a[0]), "r"(a[1]), "r"(a[2]), "r"(a[3]), "r"(b[0]), "r"(b[1]));
}

__global__ __launch_bounds__(256) void gemm_mma(
    const float* __restrict__ A, const float* __restrict__ B,
    const float* __restrict__ bias, const float* __restrict__ resid,
    const float* __restrict__ skipv, int nid,
    float* __restrict__ C, int M) {
    extern __shared__ float sm[];
    const int tid = threadIdx.x;
    const int m0 = blockIdx.x * 128;
    const int col0 = blockIdx.y * 128;
    const int w = tid >> 5, ln = tid & 31;
    const int rowb = (w >> 2) * 64, colb = (w & 3) * 32;
    const int lg = ln >> 2, lt = ln & 3;

    float* const Ab[2] = {sm, sm + SLAB_F};
    float* const Bb[2] = {sm + 2 * SLAB_F, sm + 3 * SLAB_F};

    float c[4][4][4];
#pragma unroll
    for (int mi = 0; mi < 4; mi++)
#pragma unroll
        for (int ni = 0; ni < 4; ni++)
#pragma unroll
            for (int r = 0; r < 4; r++) c[mi][ni][r] = 0.f;

    auto load_slab = [&](int s, int b) {
        const int k0 = s * 32;
        float* As = Ab[b];
        float* Bs = Bb[b];
#pragma unroll
        for (int i = 0; i < 4; i++) {
            int idx = tid + i * 256;
            int row = idx >> 3, kg = idx & 7;
            uint32_t da = (uint32_t)__cvta_generic_to_shared(As + row * 36 + kg * 4);
            const float* ga = A + (size_t)(m0 + row) * DD + k0 + kg * 4;
            int sz = ((m0 + row) < M) ? 16 : 0;
            asm volatile("cp.async.cg.shared.global [%0], [%1], 16, %2;\n" ::"r"(da), "l"(ga), "r"(sz));
            uint32_t db = (uint32_t)__cvta_generic_to_shared(Bs + row * 36 + kg * 4);
            const float* gb = B + (size_t)(col0 + row) * DD + k0 + kg * 4;
            asm volatile("cp.async.cg.shared.global [%0], [%1], 16;\n" ::"r"(db), "l"(gb));
        }
        asm volatile("cp.async.commit_group;\n");
    };

    load_slab(0, 0);
    for (int s = 0; s < 8; s++) {
        int b = s & 1;
        if (s < 7) {
            load_slab(s + 1, b ^ 1);
            asm volatile("cp.async.wait_group 1;\n");
        } else {
            asm volatile("cp.async.wait_group 0;\n");
        }
        __syncthreads();
        const float* As = Ab[b];
        const float* Bs = Bb[b];
#pragma unroll
        for (int ks = 0; ks < 4; ks++) {
            const int kk = ks * 8 + lt;
            uint32_t af[4][4], bf[4][2];
#pragma unroll
            for (int mi = 0; mi < 4; mi++) {
                const float* p = As + (rowb + mi * 16 + lg) * 36 + kk;
                af[mi][0] = __float_as_uint(p[0]);
                af[mi][1] = __float_as_uint(p[8 * 36]);
                af[mi][2] = __float_as_uint(p[4]);
                af[mi][3] = __float_as_uint(p[8 * 36 + 4]);
            }
#pragma unroll
            for (int ni = 0; ni < 4; ni++) {
                const float* p = Bs + (colb + ni * 8 + lg) * 36 + kk;
                bf[ni][0] = __float_as_uint(p[0]);
                bf[ni][1] = __float_as_uint(p[4]);
            }
#pragma unroll
            for (int mi = 0; mi < 4; mi++)
#pragma unroll
                for (int ni = 0; ni < 4; ni++) mma1688(c[mi][ni], af[mi], bf[ni]);
        }
        __syncthreads();
    }

    float alpha = 1.f, beta = 0.f;
    if (resid) {
        float sv = skipv[nid];
        alpha = 1.f / (1.f + __expf(-sv));
        beta = 1.f - alpha;
    }
#pragma unroll
    for (int mi = 0; mi < 4; mi++) {
#pragma unroll
        for (int half = 0; half < 2; half++) {
            int row = m0 + rowb + mi * 16 + lg + half * 8;
            if (row >= M) continue;
#pragma unroll
            for (int ni = 0; ni < 4; ni++) {
                int cc = col0 + colb + ni * 8 + lt * 2;
                float2 o;
                o.x = c[mi][ni][half * 2 + 0] + bias[cc];
                o.y = c[mi][ni][half * 2 + 1] + bias[cc + 1];
                if (resid) {
                    float2 rv = *(const float2*)(resid + (size_t)row * DD + cc);
                    o.x = o.x * alpha + rv.x * beta;
                    o.y = o.y * alpha + rv.y * beta;
                }
                *(float2*)(C + (size_t)row * DD + cc) = o;
            }
        }
    }
}

// ---------------- fused 3-B projection GEMM: shares A slab across 3 weights ----------------
__global__ __launch_bounds__(256, 1) void gemm3(
    const float* __restrict__ A,
    const float* __restrict__ B0, const float* __restrict__ B1, const float* __restrict__ B2,
    const float* __restrict__ bi0, const float* __restrict__ bi1, const float* __restrict__ bi2,
    float* __restrict__ C0, float* __restrict__ C1, float* __restrict__ C2, int M) {
    extern __shared__ float sm[];
    const int tid = threadIdx.x;
    const int m0 = blockIdx.x * 128;
    const int col0 = blockIdx.y * 128;
    const int w = tid >> 5, ln = tid & 31;
    const int rowb = (w >> 2) * 64, colb = (w & 3) * 32;
    const int lg = ln >> 2, lt = ln & 3;

    const float* const Bv[3] = {B0, B1, B2};
    const float* const biv[3] = {bi0, bi1, bi2};
    float* const Cv[3] = {C0, C1, C2};

    float c[3][4][4][4];
#pragma unroll
    for (int b = 0; b < 3; b++)
#pragma unroll
        for (int mi = 0; mi < 4; mi++)
#pragma unroll
            for (int ni = 0; ni < 4; ni++)
#pragma unroll
                for (int r = 0; r < 4; r++) c[b][mi][ni][r] = 0.f;

    auto load_slab = [&](int s, int buf) {
        const int k0 = s * 32;
        float* As = sm + buf * SLAB_F;
#pragma unroll
        for (int i = 0; i < 4; i++) {
            int idx = tid + i * 256;
            int row = idx >> 3, kg = idx & 7;
            uint32_t da = (uint32_t)__cvta_generic_to_shared(As + row * 36 + kg * 4);
            const float* ga = A + (size_t)(m0 + row) * DD + k0 + kg * 4;
            int sz = ((m0 + row) < M) ? 16 : 0;
            asm volatile("cp.async.cg.shared.global [%0], [%1], 16, %2;\n" ::"r"(da), "l"(ga), "r"(sz));
        }
#pragma unroll
        for (int b = 0; b < 3; b++) {
            float* Bs = sm + (2 + b * 2 + buf) * SLAB_F;
#pragma unroll
            for (int i = 0; i < 4; i++) {
                int idx = tid + i * 256;
                int row = idx >> 3, kg = idx & 7;
                uint32_t db = (uint32_t)__cvta_generic_to_shared(Bs + row * 36 + kg * 4);
                const float* gb = Bv[b] + (size_t)(col0 + row) * DD + k0 + kg * 4;
                asm volatile("cp.async.cg.shared.global [%0], [%1], 16;\n" ::"r"(db), "l"(gb));
            }
        }
        asm volatile("cp.async.commit_group;\n");
    };

    load_slab(0, 0);
    for (int s = 0; s < 8; s++) {
        int buf = s & 1;
        if (s < 7) {
            load_slab(s + 1, buf ^ 1);
            asm volatile("cp.async.wait_group 1;\n");
        } else {
            asm volatile("cp.async.wait_group 0;\n");
        }
        __syncthreads();
        const float* As = sm + buf * SLAB_F;
#pragma unroll
        for (int ks = 0; ks < 4; ks++) {
            const int kk = ks * 8 + lt;
            uint32_t af[4][4];
#pragma unroll
            for (int mi = 0; mi < 4; mi++) {
                const float* p = As + (rowb + mi * 16 + lg) * 36 + kk;
                af[mi][0] = __float_as_uint(p[0]);
                af[mi][1] = __float_as_uint(p[8 * 36]);
                af[mi][2] = __float_as_uint(p[4]);
                af[mi][3] = __float_as_uint(p[8 * 36 + 4]);
            }
#pragma unroll
            for (int b = 0; b < 3; b++) {
                const float* Bs = sm + (2 + b * 2 + buf) * SLAB_F;
                uint32_t bf[4][2];
#pragma unroll
                for (int ni = 0; ni < 4; ni++) {
                    const float* p = Bs + (colb + ni * 8 + lg) * 36 + kk;
                    bf[ni][0] = __float_as_uint(p[0]);
                    bf[ni][1] = __float_as_uint(p[4]);
                }
#pragma unroll
                for (int mi = 0; mi < 4; mi++)
#pragma unroll
                    for (int ni = 0; ni < 4; ni++) mma1688(c[b][mi][ni], af[mi], bf[ni]);
            }
        }
        __syncthreads();
    }

#pragma unroll
    for (int b = 0; b < 3; b++) {
#pragma unroll
        for (int mi = 0; mi < 4; mi++) {
#pragma unroll
            for (int half = 0; half < 2; half++) {
                int row = m0 + rowb + mi * 16 + lg + half * 8;
                if (row >= M) continue;
#pragma unroll
                for (int ni = 0; ni < 4; ni++) {
                    int cc = col0 + colb + ni * 8 + lt * 2;
                    float2 o;
                    o.x = c[b][mi][ni][half * 2 + 0] + biv[b][cc];
                    o.y = c[b][mi][ni][half * 2 + 1] + biv[b][cc + 1];
                    *(float2*)(Cv[b] + (size_t)row * DD + cc) = o;
                }
            }
        }
    }
}

// ---------------- CSR build (merged) ----------------
__global__ void zero3(int* d0, int* d1, int* d2) {
    int i = blockIdx.x * blockDim.x + threadIdx.x;
    if (i < NP) { d0[i] = 0; d1[i] = 0; }
    if (i < NA) d2[i] = 0;
}

__global__ void hist3(const int* __restrict__ dw, const int* __restrict__ dc,
                      const int* __restrict__ db, int E,
                      int* d0, int* d1, int* d2) {
    int i = blockIdx.x * blockDim.x + threadIdx.x;
    if (i < E) atomicAdd(&d0[dw[i]], 1);
    else if (i < 2 * E) atomicAdd(&d1[dc[i - E]], 1);
    else if (i < 3 * E) atomicAdd(&d2[db[i - 2 * E]], 1);
}

__global__ void scan3(const int* __restrict__ deg0, const int* __restrict__ deg1,
                      const int* __restrict__ deg2,
                      int* rp0, int* rp1, int* rp2, int* c0, int* c1, int* c2) {
    __shared__ int sh[1024];
    __shared__ int carry_s;
    const int* deg; int* rp; int* cur; int n;
    if (blockIdx.x == 0) { deg = deg0; rp = rp0; cur = c0; n = NP; }
    else if (blockIdx.x == 1) { deg = deg1; rp = rp1; cur = c1; n = NP; }
    else { deg = deg2; rp = rp2; cur = c2; n = NA; }
    int tid = threadIdx.x;
    if (tid == 0) carry_s = 0;
    __syncthreads();
    for (int base = 0; base < n; base += 1024) {
        int i = base + tid;
        int v = (i < n) ? deg[i] : 0;
        sh[tid] = v;
        __syncthreads();
        for (int off = 1; off < 1024; off <<= 1) {
            int t = (tid >= off) ? sh[tid - off] : 0;
            __syncthreads();
            sh[tid] += t;
            __syncthreads();
        }
        int incl = sh[tid] + carry_s;
        if (i < n) { rp[i + 1] = incl; cur[i] = incl - v; }
        __syncthreads();
        if (tid == 1023) carry_s = incl;
        __syncthreads();
    }
    if (tid == 0) rp[0] = 0;
}

__global__ void scatter3(const int* __restrict__ sw, const int* __restrict__ dw,
                         const int* __restrict__ sc, const int* __restrict__ dc,
                         const int* __restrict__ sb, const int* __restrict__ db, int E,
                         int* c0, int* c1, int* c2,
                         int* col0, int* col1, int* col2) {
    int i = blockIdx.x * blockDim.x + threadIdx.x;
    if (i < E) { int p = atomicAdd(&c0[dw[i]], 1); col0[p] = sw[i]; }
    else if (i < 2 * E) { int j = i - E; int p = atomicAdd(&c1[dc[j]], 1); col1[p] = sc[j]; }
    else if (i < 3 * E) { int j = i - 2 * E; int p = atomicAdd(&c2[db[j]], 1); col2[p] = sb[j]; }
}

// ---------------- per-dst online-softmax aggregation (R5 branchless) ----------------
__device__ __forceinline__ void csr_attend(
    int d, int lane, const int* __restrict__ rp, const int* __restrict__ colv,
    const float* __restrict__ K, const float* __restrict__ V,
    const float pri[NH], const float q[NH], float acc[NH]) {
    float m[NH], s[NH], a[NH];
#pragma unroll
    for (int h = 0; h < NH; h++) { m[h] = -1e30f; s[h] = 0.f; a[h] = 0.f; }
    int beg = rp[d], end = rp[d + 1];
    for (int e = beg; e < end; e++) {
        int src = colv[e];
        const float* kr = K + (size_t)src * DD;
        const float* vr = V + (size_t)src * DD;
        float p[NH];
#pragma unroll
        for (int h = 0; h < NH; h++) p[h] = q[h] * kr[h * DKH + lane];
#pragma unroll
        for (int off = 16; off; off >>= 1)
#pragma unroll
            for (int h = 0; h < NH; h++) p[h] += __shfl_xor_sync(0xffffffffu, p[h], off);
#pragma unroll
        for (int h = 0; h < NH; h++) {
            float sc = p[h] * pri[h];
            float nm = fmaxf(m[h], sc);
            float f = __expf(m[h] - nm);
            float wgt = __expf(sc - nm);
            s[h] = s[h] * f + wgt;
            a[h] = a[h] * f + wgt * vr[h * DKH + lane];
            m[h] = nm;
        }
    }
#pragma unroll
    for (int h = 0; h < NH; h++)
        if (s[h] > 0.f) acc[h] += a[h] / s[h];
}

__global__ void agg_paper_kernel(const float* __restrict__ Qp, const float* __restrict__ Qpc,
                                 const float* __restrict__ K0, const float* __restrict__ V0,
                                 const float* __restrict__ Kp, const float* __restrict__ Vp,
                                 const int* __restrict__ rp0, const int* __restrict__ col0,
                                 const int* __restrict__ rp1, const int* __restrict__ col1,
                                 const float* __restrict__ rel_pri,
                                 float* __restrict__ aggw, float* __restrict__ aggc) {
    int w = (blockIdx.x * blockDim.x + threadIdx.x) >> 5;
    int lane = threadIdx.x & 31;
    if (w >= NP) return;
    const float sc = 0.17677669529663687f;
    float q0[NH], qc[NH], accw[NH], accc[NH], pri0[NH], pri1[NH];
#pragma unroll
    for (int h = 0; h < NH; h++) {
        q0[h] = Qp[(size_t)w * DD + h * DKH + lane];
        qc[h] = Qpc[(size_t)w * DD + h * DKH + lane];
        accw[h] = 0.f; accc[h] = 0.f;
        pri0[h] = rel_pri[h] * sc;
        pri1[h] = rel_pri[NH + h] * sc;
    }
    csr_attend(w, lane, rp0, col0, K0, V0, pri0, q0, accw);
    csr_attend(w, lane, rp1, col1, Kp, Vp, pri1, qc, accc);
#pragma unroll
    for (int h = 0; h < NH; h++) {
        aggw[(size_t)w * DD + h * DKH + lane] = accw[h];
        aggc[(size_t)w * DD + h * DKH + lane] = accc[h];
    }
}

__global__ void agg_author_kernel(const float* __restrict__ Qa,
                                  const float* __restrict__ Kp, const float* __restrict__ Vp,
                                  const int* __restrict__ rp2, const int* __restrict__ col2,
                                  const float* __restrict__ rel_pri,
                                  float* __restrict__ agg) {
    int w = (blockIdx.x * blockDim.x + threadIdx.x) >> 5;
    int lane = threadIdx.x & 31;
    if (w >= NA) return;
    const float sc = 0.17677669529663687f;
    float q[NH], acc[NH], pri2[NH];
#pragma unroll
    for (int h = 0; h < NH; h++) {
        q[h] = Qa[(size_t)w * DD + h * DKH + lane];
        acc[h] = 0.f;
        pri2[h] = rel_pri[2 * NH + h] * sc;
    }
    csr_attend(w, lane, rp2, col2, Kp, Vp, pri2, q, acc);
#pragma unroll
    for (int h = 0; h < NH; h++) agg[(size_t)w * DD + h * DKH + lane] = acc[h];
}

// ---------------- host launch ----------------
extern "C" void kernel_launch(void* const* d_in, const int* in_sizes, int n_in,
                              void* d_out, int out_size) {
    const float* h_author = (const float*)d_in[0];
    const float* h_paper  = (const float*)d_in[1];
    const float* k_w  = (const float*)d_in[2];
    const float* k_b  = (const float*)d_in[3];
    const float* q_w  = (const float*)d_in[4];
    const float* q_b  = (const float*)d_in[5];
    const float* v_w  = (const float*)d_in[6];
    const float* v_b  = (const float*)d_in[7];
    const float* a_w  = (const float*)d_in[8];
    const float* a_b  = (const float*)d_in[9];
    const float* rel_att = (const float*)d_in[10];
    const float* rel_msg = (const float*)d_in[11];
    const float* rel_pri = (const float*)d_in[12];
    const float* skipv   = (const float*)d_in[13];
    const int* src_writes = (const int*)d_in[14];
    const int* dst_writes = (const int*)d_in[15];
    const int* src_cites  = (const int*)d_in[16];
    const int* dst_cites  = (const int*)d_in[17];
    const int* src_wb     = (const int*)d_in[18];
    const int* dst_wb     = (const int*)d_in[19];

    int E = in_sizes[14];
    if (E > EMAX) E = EMAX;

    float *Har, *Hpr, *K0, *V0, *Qa, *Kp, *Vp, *Qp, *Qpc;
    float *aggPw, *aggPc, *aggP, *aggAc, *aggA, *fW, *fB, *rw;
    int *deg0, *deg1, *deg2, *rp0, *rp1, *rp2, *cur0, *cur1, *cur2, *col0, *col1, *col2;
    cudaGetSymbolAddress((void**)&Har, g_Har);
    cudaGetSymbolAddress((void**)&Hpr, g_Hpr);
    cudaGetSymbolAddress((void**)&K0, g_K0);
    cudaGetSymbolAddress((void**)&V0, g_V0);
    cudaGetSymbolAddress((void**)&Qa, g_Qa);
    cudaGetSymbolAddress((void**)&Kp, g_Kp);
    cudaGetSymbolAddress((void**)&Vp, g_Vp);
    cudaGetSymbolAddress((void**)&Qp, g_Qp);
    cudaGetSymbolAddress((void**)&Qpc, g_Qpc);
    cudaGetSymbolAddress((void**)&aggPw, g_aggPw);
    cudaGetSymbolAddress((void**)&aggPc, g_aggPc);
    cudaGetSymbolAddress((void**)&aggP, g_aggP);
    cudaGetSymbolAddress((void**)&aggAc, g_aggAc);
    cudaGetSymbolAddress((void**)&aggA, g_aggA);
    cudaGetSymbolAddress((void**)&fW, g_fW);
    cudaGetSymbolAddress((void**)&fB, g_fB);
    cudaGetSymbolAddress((void**)&rw, g_rw);
    cudaGetSymbolAddress((void**)&deg0, g_deg0);
    cudaGetSymbolAddress((void**)&deg1, g_deg1);
    cudaGetSymbolAddress((void**)&deg2, g_deg2);
    cudaGetSymbolAddress((void**)&rp0, g_rp0);
    cudaGetSymbolAddress((void**)&rp1, g_rp1);
    cudaGetSymbolAddress((void**)&rp2, g_rp2);
    cudaGetSymbolAddress((void**)&cur0, g_cur0);
    cudaGetSymbolAddress((void**)&cur1, g_cur1);
    cudaGetSymbolAddress((void**)&cur2, g_cur2);
    cudaGetSymbolAddress((void**)&col0, g_col0);
    cudaGetSymbolAddress((void**)&col1, g_col1);
    cudaGetSymbolAddress((void**)&col2, g_col2);

    cudaFuncSetAttribute(gemm_mma, cudaFuncAttributeMaxDynamicSharedMemorySize, GSMEM);
    cudaFuncSetAttribute(gemm3, cudaFuncAttributeMaxDynamicSharedMemorySize, GS3);

    float* kwr1 = rw + 0 * 65536;
    float* vwr1 = rw + 1 * 65536;
    float* qwr1 = rw + 2 * 65536;
    float* awr  = rw + 3 * 65536;
    float* fWk0 = fW + 0 * 65536;
    float* fWv0 = fW + 1 * 65536;
    float* fWqa = fW + 2 * 65536;
    float* fBk0 = fB + 0 * 256;
    float* fBv0 = fB + 1 * 256;
    float* fBqa = fB + 2 * 256;

    // 1) pre-round GEMM inputs to tf32
    roundcopy<<<(NA * DD / 4 + 255) / 256, 256>>>(h_author, Har, NA * DD / 4);
    roundcopy<<<(NP * DD / 4 + 255) / 256, 256>>>(h_paper, Hpr, NP * DD / 4);
    roundcopy<<<(65536 / 4 + 255) / 256, 256>>>(k_w + 65536, kwr1, 65536 / 4);
    roundcopy<<<(65536 / 4 + 255) / 256, 256>>>(v_w + 65536, vwr1, 65536 / 4);
    roundcopy<<<(65536 / 4 + 255) / 256, 256>>>(q_w + 65536, qwr1, 65536 / 4);
    roundcopy<<<(131072 / 4 + 255) / 256, 256>>>(a_w, awr, 131072 / 4);

    // 2) weight folds
    fold_k<<<256, 256>>>(k_w, rel_att, k_b, fWk0, fBk0);
    fold_k<<<256, 256>>>(v_w, rel_msg, v_b, fWv0, fBv0);
    fold_q<<<256, 256>>>(q_w, rel_att + 2 * 8192, q_b, fWqa, fBqa);

    // 3) projection GEMMs — fused 3-B per node type
    {
        dim3 ga((NA + 127) / 128, 2), gp((NP + 127) / 128, 2);
        gemm3<<<ga, 256, GS3>>>(Har, fWk0, fWv0, fWqa, fBk0, fBv0, fBqa, K0, V0, Qa, NA);
        gemm3<<<gp, 256, GS3>>>(Hpr, kwr1, vwr1, qwr1, k_b + 256, v_b + 256, q_b + 256,
                                Kp, Vp, Qp, NP);
    }

    // 4) Q transform for cites
    {
        dim3 g((NP + 63) / 64, NH);
        bdtrans<<<g, 256>>>(Qp, nullptr, rel_att + 8192, Qpc, NP, 0, 0);
    }

    // 5) CSR builds
    zero3<<<(NP + 255) / 256, 256>>>(deg0, deg1, deg2);
    hist3<<<(3 * E + 255) / 256, 256>>>(dst_writes, dst_cites, dst_wb, E, deg0, deg1, deg2);
    scan3<<<3, 1024>>>(deg0, deg1, deg2, rp0, rp1, rp2, cur0, cur1, cur2);
    scatter3<<<(3 * E + 255) / 256, 256>>>(src_writes, dst_writes, src_cites, dst_cites,
                                           src_wb, dst_wb, E, cur0, cur1, cur2, col0, col1, col2);

    // 6) attention aggregation
    agg_paper_kernel<<<(NP * 32 + 255) / 256, 256>>>(Qp, Qpc, K0, V0, Kp, Vp,
                                                     rp0, col0, rp1, col1, rel_pri, aggPw, aggPc);
    agg_author_kernel<<<(NA * 32 + 255) / 256, 256>>>(Qa, Kp, Vp, rp2, col2, rel_pri, aggAc);

    // 7) post-agg message transforms
    {
        dim3 gp((NP + 63) / 64, NH), ga((NA + 63) / 64, NH);
        bdtrans<<<gp, 256>>>(aggPc, aggPw, rel_msg + 8192, aggP, NP, 1, 1);
        bdtrans<<<ga, 256>>>(aggAc, nullptr, rel_msg + 2 * 8192, aggA, NA, 1, 1);
    }

    // 8) output GEMMs
    float* out = (float*)d_out;
    {
        dim3 ga((NA + 127) / 128, 2), gp((NP + 127) / 128, 2);
        gemm_mma<<<ga, 256, GSMEM>>>(aggA, awr, a_b, h_author, skipv, 0, out, NA);
        gemm_mma<<<gp, 256, GSMEM>>>(aggP, awr + 65536, a_b + 256, h_paper, skipv, 1,
                                     out + (size_t)NA * DD, NP);
    }
}

// round 8
// speedup vs baseline: 1.6220x; 1.2516x over previous
#include <cuda_runtime.h>
#include <math.h>
#include <cstdint>

#define NA 20000
#define NP 50000
#define EMAX 300000
#define DD 256
#define NH 8
#define DKH 32

// ---------------- scratch (static __device__ globals) ----------------
__device__ float g_Har[NA * DD];
__device__ float g_Hpr[NP * DD];
__device__ float g_K0[NA * DD];
__device__ float g_V0[NA * DD];
__device__ float g_Qa[NA * DD];
__device__ float g_Kp[NP * DD];
__device__ float g_Vp[NP * DD];
__device__ float g_Qp[NP * DD];
__device__ float g_Qpc[NP * DD];
__device__ float g_aggPw[NP * DD];
__device__ float g_aggPc[NP * DD];
__device__ float g_aggP[NP * DD];
__device__ float g_aggAc[NA * DD];
__device__ float g_aggA[NA * DD];
__device__ float g_fW[3 * DD * DD];
__device__ float g_fB[3 * DD];
__device__ float g_rw[5 * DD * DD];
__device__ int g_deg0[NP];
__device__ int g_deg1[NP];
__device__ int g_deg2[NA];
__device__ int g_rp0[NP + 1];
__device__ int g_rp1[NP + 1];
__device__ int g_rp2[NA + 1];
__device__ int g_cur0[NP];
__device__ int g_cur1[NP];
__device__ int g_cur2[NA];
__device__ int g_col0[EMAX];
__device__ int g_col1[EMAX];
__device__ int g_col2[EMAX];

__device__ __forceinline__ float tf32r(float v) {
    uint32_t r;
    asm("cvt.rna.tf32.f32 %0, %1;" : "=r"(r) : "f"(v));
    return __uint_as_float(r);
}

// ---------------- round-copy ----------------
__global__ void roundcopy(const float* __restrict__ in, float* __restrict__ out, int n4) {
    int i = blockIdx.x * blockDim.x + threadIdx.x;
    if (i < n4) {
        float4 v = ((const float4*)in)[i];
        v.x = tf32r(v.x); v.y = tf32r(v.y); v.z = tf32r(v.z); v.w = tf32r(v.w);
        ((float4*)out)[i] = v;
    }
}

// ---------------- weight folds ----------------
__global__ void fold_k(const float* __restrict__ W, const float* __restrict__ rel,
                       const float* __restrict__ b,
                       float* __restrict__ Wout, float* __restrict__ bout) {
    int c = blockIdx.x, d = threadIdx.x;
    int h = c >> 5, j = c & 31;
    float s = 0.f;
#pragma unroll
    for (int i = 0; i < 32; i++)
        s += rel[(h * 32 + i) * 32 + j] * W[(h * 32 + i) * DD + d];
    Wout[c * DD + d] = tf32r(s);
    if (d == 0) {
        float sb = 0.f;
#pragma unroll
        for (int i = 0; i < 32; i++)
            sb += rel[(h * 32 + i) * 32 + j] * b[h * 32 + i];
        bout[c] = sb;
    }
}

__global__ void fold_q(const float* __restrict__ W, const float* __restrict__ rel,
                       const float* __restrict__ b,
                       float* __restrict__ Wout, float* __restrict__ bout) {
    int c = blockIdx.x, d = threadIdx.x;
    int h = c >> 5, i = c & 31;
    float s = 0.f;
#pragma unroll
    for (int j = 0; j < 32; j++)
        s += rel[(h * 32 + i) * 32 + j] * W[(h * 32 + j) * DD + d];
    Wout[c * DD + d] = tf32r(s);
    if (d == 0) {
        float sb = 0.f;
#pragma unroll
        for (int j = 0; j < 32; j++)
            sb += rel[(h * 32 + i) * 32 + j] * b[h * 32 + j];
        bout[c] = sb;
    }
}

// ---------------- block-diagonal per-head transform ----------------
__global__ void bdtrans(const float* __restrict__ in, const float* __restrict__ base,
                        const float* __restrict__ R, float* __restrict__ out,
                        int N, int transp, int roundit) {
    __shared__ float Rs[32 * 33];
    __shared__ float As[64 * 33];
    const int h = blockIdx.y;
    const int n0 = blockIdx.x * 64;
    const int t = threadIdx.x;
#pragma unroll
    for (int k = 0; k < 4; k++) {
        int idx = t * 4 + k;
        int i0 = idx >> 5, j0 = idx & 31;
        float v = R[h * 1024 + idx];
        if (transp) Rs[i0 * 33 + j0] = v;
        else        Rs[j0 * 33 + i0] = v;
    }
    const int rows = (N - n0 < 64) ? (N - n0) : 64;
#pragma unroll
    for (int it = 0; it < 8; it++) {
        int r = (t >> 5) + it * 8;
        int j = t & 31;
        if (r < rows) As[r * 33 + j] = in[(size_t)(n0 + r) * DD + h * 32 + j];
    }
    __syncthreads();
    const int i = t & 31;
#pragma unroll
    for (int it = 0; it < 8; it++) {
        int r = (t >> 5) + it * 8;
        if (r >= rows) break;
        float v = 0.f;
#pragma unroll
        for (int j = 0; j < 32; j++) v += As[r * 33 + j] * Rs[j * 33 + i];
        size_t o = (size_t)(n0 + r) * DD + h * 32 + i;
        if (base) v += base[o];
        out[o] = roundit ? tf32r(v) : v;
    }
}

// ---------------- tf32 mma GEMM (single-B) ----------------
#define SLAB_F (128 * 36)
#define GSMEM (4 * SLAB_F * 4)
#define GS3 (8 * SLAB_F * 4)

__device__ __forceinline__ void mma1688(float c[4], const uint32_t a[4], const uint32_t b[2]) {
    asm volatile(
        "mma.sync.aligned.m16n8k8.row.col.f32.tf32.tf32.f32 "
        "{%0,%1,%2,%3}, {%4,%5,%6,%7}, {%8,%9}, {%0,%1,%2,%3};"
        : "+f"(c[0]), "+f"(c[1]), "+f"(c[2]), "+f"(c[3])
        : "r"(a[0]), "r"(a[1]), "r"(a[2]), "r"(a[3]), "r"(b[0]), "r"(b[1]));
}

__global__ __launch_bounds__(256) void gemm_mma(
    const float* __restrict__ A, const float* __restrict__ B,
    const float* __restrict__ bias, const float* __restrict__ resid,
    const float* __restrict__ skipv, int nid,
    float* __restrict__ C, int M) {
    extern __shared__ float sm[];
    const int tid = threadIdx.x;
    const int m0 = blockIdx.x * 128;
    const int col0 = blockIdx.y * 128;
    const int w = tid >> 5, ln = tid & 31;
    const int rowb = (w >> 2) * 64, colb = (w & 3) * 32;
    const int lg = ln >> 2, lt = ln & 3;

    float* const Ab[2] = {sm, sm + SLAB_F};
    float* const Bb[2] = {sm + 2 * SLAB_F, sm + 3 * SLAB_F};

    float c[4][4][4];
#pragma unroll
    for (int mi = 0; mi < 4; mi++)
#pragma unroll
        for (int ni = 0; ni < 4; ni++)
#pragma unroll
            for (int r = 0; r < 4; r++) c[mi][ni][r] = 0.f;

    auto load_slab = [&](int s, int b) {
        const int k0 = s * 32;
        float* As = Ab[b];
        float* Bs = Bb[b];
#pragma unroll
        for (int i = 0; i < 4; i++) {
            int idx = tid + i * 256;
            int row = idx >> 3, kg = idx & 7;
            uint32_t da = (uint32_t)__cvta_generic_to_shared(As + row * 36 + kg * 4);
            const float* ga = A + (size_t)(m0 + row) * DD + k0 + kg * 4;
            int sz = ((m0 + row) < M) ? 16 : 0;
            asm volatile("cp.async.cg.shared.global [%0], [%1], 16, %2;\n" ::"r"(da), "l"(ga), "r"(sz));
            uint32_t db = (uint32_t)__cvta_generic_to_shared(Bs + row * 36 + kg * 4);
            const float* gb = B + (size_t)(col0 + row) * DD + k0 + kg * 4;
            asm volatile("cp.async.cg.shared.global [%0], [%1], 16;\n" ::"r"(db), "l"(gb));
        }
        asm volatile("cp.async.commit_group;\n");
    };

    load_slab(0, 0);
    for (int s = 0; s < 8; s++) {
        int b = s & 1;
        if (s < 7) {
            load_slab(s + 1, b ^ 1);
            asm volatile("cp.async.wait_group 1;\n");
        } else {
            asm volatile("cp.async.wait_group 0;\n");
        }
        __syncthreads();
        const float* As = Ab[b];
        const float* Bs = Bb[b];
#pragma unroll
        for (int ks = 0; ks < 4; ks++) {
            const int kk = ks * 8 + lt;
            uint32_t af[4][4], bf[4][2];
#pragma unroll
            for (int mi = 0; mi < 4; mi++) {
                const float* p = As + (rowb + mi * 16 + lg) * 36 + kk;
                af[mi][0] = __float_as_uint(p[0]);
                af[mi][1] = __float_as_uint(p[8 * 36]);
                af[mi][2] = __float_as_uint(p[4]);
                af[mi][3] = __float_as_uint(p[8 * 36 + 4]);
            }
#pragma unroll
            for (int ni = 0; ni < 4; ni++) {
                const float* p = Bs + (colb + ni * 8 + lg) * 36 + kk;
                bf[ni][0] = __float_as_uint(p[0]);
                bf[ni][1] = __float_as_uint(p[4]);
            }
#pragma unroll
            for (int mi = 0; mi < 4; mi++)
#pragma unroll
                for (int ni = 0; ni < 4; ni++) mma1688(c[mi][ni], af[mi], bf[ni]);
        }
        __syncthreads();
    }

    float alpha = 1.f, beta = 0.f;
    if (resid) {
        float sv = skipv[nid];
        alpha = 1.f / (1.f + __expf(-sv));
        beta = 1.f - alpha;
    }
#pragma unroll
    for (int mi = 0; mi < 4; mi++) {
#pragma unroll
        for (int half = 0; half < 2; half++) {
            int row = m0 + rowb + mi * 16 + lg + half * 8;
            if (row >= M) continue;
#pragma unroll
            for (int ni = 0; ni < 4; ni++) {
                int cc = col0 + colb + ni * 8 + lt * 2;
                float2 o;
                o.x = c[mi][ni][half * 2 + 0] + bias[cc];
                o.y = c[mi][ni][half * 2 + 1] + bias[cc + 1];
                if (resid) {
                    float2 rv = *(const float2*)(resid + (size_t)row * DD + cc);
                    o.x = o.x * alpha + rv.x * beta;
                    o.y = o.y * alpha + rv.y * beta;
                }
                *(float2*)(C + (size_t)row * DD + cc) = o;
            }
        }
    }
}

// ---------------- fused 3-B projection GEMM ----------------
__global__ __launch_bounds__(256, 1) void gemm3(
    const float* __restrict__ A,
    const float* __restrict__ B0, const float* __restrict__ B1, const float* __restrict__ B2,
    const float* __restrict__ bi0, const float* __restrict__ bi1, const float* __restrict__ bi2,
    float* __restrict__ C0, float* __restrict__ C1, float* __restrict__ C2, int M) {
    extern __shared__ float sm[];
    const int tid = threadIdx.x;
    const int m0 = blockIdx.x * 128;
    const int col0 = blockIdx.y * 128;
    const int w = tid >> 5, ln = tid & 31;
    const int rowb = (w >> 2) * 64, colb = (w & 3) * 32;
    const int lg = ln >> 2, lt = ln & 3;

    const float* const Bv[3] = {B0, B1, B2};
    const float* const biv[3] = {bi0, bi1, bi2};
    float* const Cv[3] = {C0, C1, C2};

    float c[3][4][4][4];
#pragma unroll
    for (int b = 0; b < 3; b++)
#pragma unroll
        for (int mi = 0; mi < 4; mi++)
#pragma unroll
            for (int ni = 0; ni < 4; ni++)
#pragma unroll
                for (int r = 0; r < 4; r++) c[b][mi][ni][r] = 0.f;

    auto load_slab = [&](int s, int buf) {
        const int k0 = s * 32;
        float* As = sm + buf * SLAB_F;
#pragma unroll
        for (int i = 0; i < 4; i++) {
            int idx = tid + i * 256;
            int row = idx >> 3, kg = idx & 7;
            uint32_t da = (uint32_t)__cvta_generic_to_shared(As + row * 36 + kg * 4);
            const float* ga = A + (size_t)(m0 + row) * DD + k0 + kg * 4;
            int sz = ((m0 + row) < M) ? 16 : 0;
            asm volatile("cp.async.cg.shared.global [%0], [%1], 16, %2;\n" ::"r"(da), "l"(ga), "r"(sz));
        }
#pragma unroll
        for (int b = 0; b < 3; b++) {
            float* Bs = sm + (2 + b * 2 + buf) * SLAB_F;
#pragma unroll
            for (int i = 0; i < 4; i++) {
                int idx = tid + i * 256;
                int row = idx >> 3, kg = idx & 7;
                uint32_t db = (uint32_t)__cvta_generic_to_shared(Bs + row * 36 + kg * 4);
                const float* gb = Bv[b] + (size_t)(col0 + row) * DD + k0 + kg * 4;
                asm volatile("cp.async.cg.shared.global [%0], [%1], 16;\n" ::"r"(db), "l"(gb));
            }
        }
        asm volatile("cp.async.commit_group;\n");
    };

    load_slab(0, 0);
    for (int s = 0; s < 8; s++) {
        int buf = s & 1;
        if (s < 7) {
            load_slab(s + 1, buf ^ 1);
            asm volatile("cp.async.wait_group 1;\n");
        } else {
            asm volatile("cp.async.wait_group 0;\n");
        }
        __syncthreads();
        const float* As = sm + buf * SLAB_F;
#pragma unroll
        for (int ks = 0; ks < 4; ks++) {
            const int kk = ks * 8 + lt;
            uint32_t af[4][4];
#pragma unroll
            for (int mi = 0; mi < 4; mi++) {
                const float* p = As + (rowb + mi * 16 + lg) * 36 + kk;
                af[mi][0] = __float_as_uint(p[0]);
                af[mi][1] = __float_as_uint(p[8 * 36]);
                af[mi][2] = __float_as_uint(p[4]);
                af[mi][3] = __float_as_uint(p[8 * 36 + 4]);
            }
#pragma unroll
            for (int b = 0; b < 3; b++) {
                const float* Bs = sm + (2 + b * 2 + buf) * SLAB_F;
                uint32_t bf[4][2];
#pragma unroll
                for (int ni = 0; ni < 4; ni++) {
                    const float* p = Bs + (colb + ni * 8 + lg) * 36 + kk;
                    bf[ni][0] = __float_as_uint(p[0]);
                    bf[ni][1] = __float_as_uint(p[4]);
                }
#pragma unroll
                for (int mi = 0; mi < 4; mi++)
#pragma unroll
                    for (int ni = 0; ni < 4; ni++) mma1688(c[b][mi][ni], af[mi], bf[ni]);
            }
        }
        __syncthreads();
    }

#pragma unroll
    for (int b = 0; b < 3; b++) {
#pragma unroll
        for (int mi = 0; mi < 4; mi++) {
#pragma unroll
            for (int half = 0; half < 2; half++) {
                int row = m0 + rowb + mi * 16 + lg + half * 8;
                if (row >= M) continue;
#pragma unroll
                for (int ni = 0; ni < 4; ni++) {
                    int cc = col0 + colb + ni * 8 + lt * 2;
                    float2 o;
                    o.x = c[b][mi][ni][half * 2 + 0] + biv[b][cc];
                    o.y = c[b][mi][ni][half * 2 + 1] + biv[b][cc + 1];
                    *(float2*)(Cv[b] + (size_t)row * DD + cc) = o;
                }
            }
        }
    }
}

// ---------------- CSR build (merged) ----------------
__global__ void zero3(int* d0, int* d1, int* d2) {
    int i = blockIdx.x * blockDim.x + threadIdx.x;
    if (i < NP) { d0[i] = 0; d1[i] = 0; }
    if (i < NA) d2[i] = 0;
}

__global__ void hist3(const int* __restrict__ dw, const int* __restrict__ dc,
                      const int* __restrict__ db, int E,
                      int* d0, int* d1, int* d2) {
    int i = blockIdx.x * blockDim.x + threadIdx.x;
    if (i < E) atomicAdd(&d0[dw[i]], 1);
    else if (i < 2 * E) atomicAdd(&d1[dc[i - E]], 1);
    else if (i < 3 * E) atomicAdd(&d2[db[i - 2 * E]], 1);
}

__global__ void scan3(const int* __restrict__ deg0, const int* __restrict__ deg1,
                      const int* __restrict__ deg2,
                      int* rp0, int* rp1, int* rp2, int* c0, int* c1, int* c2) {
    __shared__ int sh[1024];
    __shared__ int carry_s;
    const int* deg; int* rp; int* cur; int n;
    if (blockIdx.x == 0) { deg = deg0; rp = rp0; cur = c0; n = NP; }
    else if (blockIdx.x == 1) { deg = deg1; rp = rp1; cur = c1; n = NP; }
    else { deg = deg2; rp = rp2; cur = c2; n = NA; }
    int tid = threadIdx.x;
    if (tid == 0) carry_s = 0;
    __syncthreads();
    for (int base = 0; base < n; base += 1024) {
        int i = base + tid;
        int v = (i < n) ? deg[i] : 0;
        sh[tid] = v;
        __syncthreads();
        for (int off = 1; off < 1024; off <<= 1) {
            int t = (tid >= off) ? sh[tid - off] : 0;
            __syncthreads();
            sh[tid] += t;
            __syncthreads();
        }
        int incl = sh[tid] + carry_s;
        if (i < n) { rp[i + 1] = incl; cur[i] = incl - v; }
        __syncthreads();
        if (tid == 1023) carry_s = incl;
        __syncthreads();
    }
    if (tid == 0) rp[0] = 0;
}

__global__ void scatter3(const int* __restrict__ sw, const int* __restrict__ dw,
                         const int* __restrict__ sc, const int* __restrict__ dc,
                         const int* __restrict__ sb, const int* __restrict__ db, int E,
                         int* c0, int* c1, int* c2,
                         int* col0, int* col1, int* col2) {
    int i = blockIdx.x * blockDim.x + threadIdx.x;
    if (i < E) { int p = atomicAdd(&c0[dw[i]], 1); col0[p] = sw[i]; }
    else if (i < 2 * E) { int j = i - E; int p = atomicAdd(&c1[dc[j]], 1); col1[p] = sc[j]; }
    else if (i < 3 * E) { int j = i - 2 * E; int p = atomicAdd(&c2[db[j]], 1); col2[p] = sb[j]; }
}

// ---------------- aggregation: lane = (head=lane/4, 8 elems), direct exp ----------------
// Per edge: dot via 8 FMA + 2 shfl, 1 expf, V accumulate via 8 FMA. No loop-carried chain.
__device__ __forceinline__ void csr_attend8(
    int node, int lane, const int* __restrict__ rp, const int* __restrict__ colv,
    const float* __restrict__ K, const float* __restrict__ V,
    const float4 qa, const float4 qb, const float prih, float acc[8]) {
    float s = 0.f;
    float a[8];
#pragma unroll
    for (int j = 0; j < 8; j++) a[j] = 0.f;
    const int off = (lane >> 2) * DKH + (lane & 3) * 8;
    const int beg = rp[node], end = rp[node + 1];
    for (int e = beg; e < end; e++) {
        const int src = colv[e];
        const float* kr = K + (size_t)src * DD + off;
        float4 k0 = *(const float4*)kr;
        float4 k1 = *(const float4*)(kr + 4);
        float p = qa.x * k0.x + qa.y * k0.y + qa.z * k0.z + qa.w * k0.w +
                  qb.x * k1.x + qb.y * k1.y + qb.z * k1.z + qb.w * k1.w;
        p += __shfl_xor_sync(0xffffffffu, p, 1);
        p += __shfl_xor_sync(0xffffffffu, p, 2);
        float wgt = __expf(p * prih);
        const float* vr = V + (size_t)src * DD + off;
        float4 v0 = *(const float4*)vr;
        float4 v1 = *(const float4*)(vr + 4);
        s += wgt;
        a[0] += wgt * v0.x; a[1] += wgt * v0.y; a[2] += wgt * v0.z; a[3] += wgt * v0.w;
        a[4] += wgt * v1.x; a[5] += wgt * v1.y; a[6] += wgt * v1.z; a[7] += wgt * v1.w;
    }
    if (s > 0.f) {
        float inv = 1.f / s;
#pragma unroll
        for (int j = 0; j < 8; j++) acc[j] += a[j] * inv;
    }
}

__global__ void agg_paper_kernel(const float* __restrict__ Qp, const float* __restrict__ Qpc,
                                 const float* __restrict__ K0, const float* __restrict__ V0,
                                 const float* __restrict__ Kp, const float* __restrict__ Vp,
                                 const int* __restrict__ rp0, const int* __restrict__ col0,
                                 const int* __restrict__ rp1, const int* __restrict__ col1,
                                 const float* __restrict__ rel_pri,
                                 float* __restrict__ aggw, float* __restrict__ aggc) {
    int w = (blockIdx.x * blockDim.x + threadIdx.x) >> 5;
    int lane = threadIdx.x & 31;
    if (w >= NP) return;
    const float sc = 0.17677669529663687f;
    const int h = lane >> 2;
    const int off = h * DKH + (lane & 3) * 8;
    const size_t qoff = (size_t)w * DD + off;
    {
        float4 qa = *(const float4*)(Qp + qoff);
        float4 qb = *(const float4*)(Qp + qoff + 4);
        float acc[8];
#pragma unroll
        for (int j = 0; j < 8; j++) acc[j] = 0.f;
        csr_attend8(w, lane, rp0, col0, K0, V0, qa, qb, rel_pri[h] * sc, acc);
        float* o = aggw + qoff;
        *(float4*)o = make_float4(acc[0], acc[1], acc[2], acc[3]);
        *(float4*)(o + 4) = make_float4(acc[4], acc[5], acc[6], acc[7]);
    }
    {
        float4 qa = *(const float4*)(Qpc + qoff);
        float4 qb = *(const float4*)(Qpc + qoff + 4);
        float acc[8];
#pragma unroll
        for (int j = 0; j < 8; j++) acc[j] = 0.f;
        csr_attend8(w, lane, rp1, col1, Kp, Vp, qa, qb, rel_pri[NH + h] * sc, acc);
        float* o = aggc + qoff;
        *(float4*)o = make_float4(acc[0], acc[1], acc[2], acc[3]);
        *(float4*)(o + 4) = make_float4(acc[4], acc[5], acc[6], acc[7]);
    }
}

__global__ void agg_author_kernel(const float* __restrict__ Qa,
                                  const float* __restrict__ Kp, const float* __restrict__ Vp,
                                  const int* __restrict__ rp2, const int* __restrict__ col2,
                                  const float* __restrict__ rel_pri,
                                  float* __restrict__ agg) {
    int w = (blockIdx.x * blockDim.x + threadIdx.x) >> 5;
    int lane = threadIdx.x & 31;
    if (w >= NA) return;
    const float sc = 0.17677669529663687f;
    const int h = lane >> 2;
    const int off = h * DKH + (lane & 3) * 8;
    const size_t qoff = (size_t)w * DD + off;
    float4 qa = *(const float4*)(Qa + qoff);
    float4 qb = *(const float4*)(Qa + qoff + 4);
    float acc[8];
#pragma unroll
    for (int j = 0; j < 8; j++) acc[j] = 0.f;
    csr_attend8(w, lane, rp2, col2, Kp, Vp, qa, qb, rel_pri[2 * NH + h] * sc, acc);
    float* o = agg + qoff;
    *(float4*)o = make_float4(acc[0], acc[1], acc[2], acc[3]);
    *(float4*)(o + 4) = make_float4(acc[4], acc[5], acc[6], acc[7]);
}

// ---------------- host launch ----------------
extern "C" void kernel_launch(void* const* d_in, const int* in_sizes, int n_in,
                              void* d_out, int out_size) {
    const float* h_author = (const float*)d_in[0];
    const float* h_paper  = (const float*)d_in[1];
    const float* k_w  = (const float*)d_in[2];
    const float* k_b  = (const float*)d_in[3];
    const float* q_w  = (const float*)d_in[4];
    const float* q_b  = (const float*)d_in[5];
    const float* v_w  = (const float*)d_in[6];
    const float* v_b  = (const float*)d_in[7];
    const float* a_w  = (const float*)d_in[8];
    const float* a_b  = (const float*)d_in[9];
    const float* rel_att = (const float*)d_in[10];
    const float* rel_msg = (const float*)d_in[11];
    const float* rel_pri = (const float*)d_in[12];
    const float* skipv   = (const float*)d_in[13];
    const int* src_writes = (const int*)d_in[14];
    const int* dst_writes = (const int*)d_in[15];
    const int* src_cites  = (const int*)d_in[16];
    const int* dst_cites  = (const int*)d_in[17];
    const int* src_wb     = (const int*)d_in[18];
    const int* dst_wb     = (const int*)d_in[19];

    int E = in_sizes[14];
    if (E > EMAX) E = EMAX;

    float *Har, *Hpr, *K0, *V0, *Qa, *Kp, *Vp, *Qp, *Qpc;
    float *aggPw, *aggPc, *aggP, *aggAc, *aggA, *fW, *fB, *rw;
    int *deg0, *deg1, *deg2, *rp0, *rp1, *rp2, *cur0, *cur1, *cur2, *col0, *col1, *col2;
    cudaGetSymbolAddress((void**)&Har, g_Har);
    cudaGetSymbolAddress((void**)&Hpr, g_Hpr);
    cudaGetSymbolAddress((void**)&K0, g_K0);
    cudaGetSymbolAddress((void**)&V0, g_V0);
    cudaGetSymbolAddress((void**)&Qa, g_Qa);
    cudaGetSymbolAddress((void**)&Kp, g_Kp);
    cudaGetSymbolAddress((void**)&Vp, g_Vp);
    cudaGetSymbolAddress((void**)&Qp, g_Qp);
    cudaGetSymbolAddress((void**)&Qpc, g_Qpc);
    cudaGetSymbolAddress((void**)&aggPw, g_aggPw);
    cudaGetSymbolAddress((void**)&aggPc, g_aggPc);
    cudaGetSymbolAddress((void**)&aggP, g_aggP);
    cudaGetSymbolAddress((void**)&aggAc, g_aggAc);
    cudaGetSymbolAddress((void**)&aggA, g_aggA);
    cudaGetSymbolAddress((void**)&fW, g_fW);
    cudaGetSymbolAddress((void**)&fB, g_fB);
    cudaGetSymbolAddress((void**)&rw, g_rw);
    cudaGetSymbolAddress((void**)&deg0, g_deg0);
    cudaGetSymbolAddress((void**)&deg1, g_deg1);
    cudaGetSymbolAddress((void**)&deg2, g_deg2);
    cudaGetSymbolAddress((void**)&rp0, g_rp0);
    cudaGetSymbolAddress((void**)&rp1, g_rp1);
    cudaGetSymbolAddress((void**)&rp2, g_rp2);
    cudaGetSymbolAddress((void**)&cur0, g_cur0);
    cudaGetSymbolAddress((void**)&cur1, g_cur1);
    cudaGetSymbolAddress((void**)&cur2, g_cur2);
    cudaGetSymbolAddress((void**)&col0, g_col0);
    cudaGetSymbolAddress((void**)&col1, g_col1);
    cudaGetSymbolAddress((void**)&col2, g_col2);

    cudaFuncSetAttribute(gemm_mma, cudaFuncAttributeMaxDynamicSharedMemorySize, GSMEM);
    cudaFuncSetAttribute(gemm3, cudaFuncAttributeMaxDynamicSharedMemorySize, GS3);

    float* kwr1 = rw + 0 * 65536;
    float* vwr1 = rw + 1 * 65536;
    float* qwr1 = rw + 2 * 65536;
    float* awr  = rw + 3 * 65536;
    float* fWk0 = fW + 0 * 65536;
    float* fWv0 = fW + 1 * 65536;
    float* fWqa = fW + 2 * 65536;
    float* fBk0 = fB + 0 * 256;
    float* fBv0 = fB + 1 * 256;
    float* fBqa = fB + 2 * 256;

    // 1) pre-round GEMM inputs to tf32
    roundcopy<<<(NA * DD / 4 + 255) / 256, 256>>>(h_author, Har, NA * DD / 4);
    roundcopy<<<(NP * DD / 4 + 255) / 256, 256>>>(h_paper, Hpr, NP * DD / 4);
    roundcopy<<<(65536 / 4 + 255) / 256, 256>>>(k_w + 65536, kwr1, 65536 / 4);
    roundcopy<<<(65536 / 4 + 255) / 256, 256>>>(v_w + 65536, vwr1, 65536 / 4);
    roundcopy<<<(65536 / 4 + 255) / 256, 256>>>(q_w + 65536, qwr1, 65536 / 4);
    roundcopy<<<(131072 / 4 + 255) / 256, 256>>>(a_w, awr, 131072 / 4);

    // 2) weight folds
    fold_k<<<256, 256>>>(k_w, rel_att, k_b, fWk0, fBk0);
    fold_k<<<256, 256>>>(v_w, rel_msg, v_b, fWv0, fBv0);
    fold_q<<<256, 256>>>(q_w, rel_att + 2 * 8192, q_b, fWqa, fBqa);

    // 3) projection GEMMs — fused 3-B per node type
    {
        dim3 ga((NA + 127) / 128, 2), gp((NP + 127) / 128, 2);
        gemm3<<<ga, 256, GS3>>>(Har, fWk0, fWv0, fWqa, fBk0, fBv0, fBqa, K0, V0, Qa, NA);
        gemm3<<<gp, 256, GS3>>>(Hpr, kwr1, vwr1, qwr1, k_b + 256, v_b + 256, q_b + 256,
                                Kp, Vp, Qp, NP);
    }

    // 4) Q transform for cites
    {
        dim3 g((NP + 63) / 64, NH);
        bdtrans<<<g, 256>>>(Qp, nullptr, rel_att + 8192, Qpc, NP, 0, 0);
    }

    // 5) CSR builds
    zero3<<<(NP + 255) / 256, 256>>>(deg0, deg1, deg2);
    hist3<<<(3 * E + 255) / 256, 256>>>(dst_writes, dst_cites, dst_wb, E, deg0, deg1, deg2);
    scan3<<<3, 1024>>>(deg0, deg1, deg2, rp0, rp1, rp2, cur0, cur1, cur2);
    scatter3<<<(3 * E + 255) / 256, 256>>>(src_writes, dst_writes, src_cites, dst_cites,
                                           src_wb, dst_wb, E, cur0, cur1, cur2, col0, col1, col2);

    // 6) attention aggregation
    agg_paper_kernel<<<(NP * 32 + 255) / 256, 256>>>(Qp, Qpc, K0, V0, Kp, Vp,
                                                     rp0, col0, rp1, col1, rel_pri, aggPw, aggPc);
    agg_author_kernel<<<(NA * 32 + 255) / 256, 256>>>(Qa, Kp, Vp, rp2, col2, rel_pri, aggAc);

    // 7) post-agg message transforms
    {
        dim3 gp((NP + 63) / 64, NH), ga((NA + 63) / 64, NH);
        bdtrans<<<gp, 256>>>(aggPc, aggPw, rel_msg + 8192, aggP, NP, 1, 1);
        bdtrans<<<ga, 256>>>(aggAc, nullptr, rel_msg + 2 * 8192, aggA, NA, 1, 1);
    }

    // 8) output GEMMs
    float* out = (float*)d_out;
    {
        dim3 ga((NA + 127) / 128, 2), gp((NP + 127) / 128, 2);
        gemm_mma<<<ga, 256, GSMEM>>>(aggA, awr, a_b, h_author, skipv, 0, out, NA);
        gemm_mma<<<gp, 256, GSMEM>>>(aggP, awr + 65536, a_b + 256, h_paper, skipv, 1,
                                     out + (size_t)NA * DD, NP);
    }
}